// round 15
// baseline (speedup 1.0000x reference)
#include <cuda_runtime.h>
#include <cstdint>

#define DIMS   120
#define NPIX   14400        // 120*120
#define SS2    81
#define B64    64
#define PITCH  92           // weights: banks 28g+q all-distinct
#define XBP    210          // x-tile batch pitch (10 rows x 21)
#define XRP    21           // x-tile row pitch
#define V4PIX  841          // 29*29
#define FLATN  13456        // 16*841
#define PPB    10           // pixels per v1 block (same image row)

// Intermediates (allocation-free scratch)
__device__ float g_cplx[8 * NPIX * B64];    // [s][pix][b]
__device__ float g_part[V4PIX * 128];       // [p][b*2+cls] decision partials

__device__ __forceinline__ void cp_async4(void* smem_dst, const void* gmem_src) {
    unsigned s = (unsigned)__cvta_generic_to_shared(smem_dst);
    asm volatile("cp.async.ca.shared.global [%0], [%1], 4;" :: "r"(s), "l"(gmem_src));
}
__device__ __forceinline__ void cp_async16(void* smem_dst, const void* gmem_src) {
    unsigned s = (unsigned)__cvta_generic_to_shared(smem_dst);
    asm volatile("cp.async.cg.shared.global [%0], [%1], 16;" :: "r"(s), "l"(gmem_src));
}
__device__ __forceinline__ void cp_commit() {
    asm volatile("cp.async.commit_group;");
}
__device__ __forceinline__ uint32_t to_tf32(float f) {
    uint32_t r;
    asm("cvt.rna.tf32.f32 %0, %1;" : "=r"(r) : "f"(f));
    return r;
}
__device__ __forceinline__ float4 cvt4(float4 v) {
    float4 o;
    o.x = __uint_as_float(to_tf32(v.x));
    o.y = __uint_as_float(to_tf32(v.y));
    o.z = __uint_as_float(to_tf32(v.z));
    o.w = __uint_as_float(to_tf32(v.w));
    return o;
}

// ---------------------------------------------------------------------------
// V1 via mma.sync m16n8k8 tf32, 256 threads. x-tile staged AND pre-converted
// to tf32 once per block; each weight buffer pre-converted once per pixel.
// GEMM loop has zero cvt instructions.
// Warp w: m-tile = w>>1 (batches 16mt..), n-half = w&1 (n-tiles 2nh,2nh+1).
// ---------------------------------------------------------------------------
__global__ __launch_bounds__(256)
void v1_kernel(const float* __restrict__ x, const float* __restrict__ w)
{
    extern __shared__ __align__(16) float sm[];
    float (*w_s)[32][PITCH] = (float (*)[32][PITCH])sm;         // [2][32][92]
    float* xt               = sm + 2 * 32 * PITCH;              // [64][210]
    float* bounce           = sm + 2 * 32 * PITCH + B64 * XBP;  // [8*64]

    int t = threadIdx.x;
    int lane = t & 31, wid = t >> 5;
    int g = lane >> 2;
    int q = lane & 3;
    int mt = wid >> 1;          // m-tile (batch group)
    int nh = wid & 1;           // n-half

    int row_i = blockIdx.x / 12;
    int j0    = (blockIdx.x % 12) * 10;
    int p0    = row_i * DIMS + j0;

    // zero weight k-padding cols 81..91 (both buffers)
    if (t < 64) {
        float* rowp = &w_s[t >> 5][t & 31][0];
#pragma unroll
        for (int c = 81; c < 92; c++) rowp[c] = 0.f;
    }
    // zero x-tile pad row r=9
    for (int idx = t; idx < B64 * XRP; idx += 256)
        xt[(idx / XRP) * XBP + 9 * XRP + (idx % XRP)] = 0.f;

    // per-thread A-fragment offsets: offA(k) = (k/9)*21 + k%9
    int offA1[11], offA2[11];
#pragma unroll
    for (int kt = 0; kt < 11; kt++) {
        int k1 = kt * 8 + q;
        int k2 = k1 + 4;
        offA1[kt] = (k1 / 9) * XRP + (k1 % 9);
        offA2[kt] = (k2 / 9) * XRP + (k2 % 9);
    }

    // weight staging: pixel p -> w_s[buf][c][k]; 8 warps x 4 channels
    auto wpre = [&](int p, int buf) {
#pragma unroll
        for (int gg = 0; gg < 4; gg++) {
            int c = wid * 4 + gg;
            const float* src = w + (c * NPIX + p) * SS2 + lane;
            float* dst = &w_s[buf][c][lane];
            cp_async4(dst, src);
            cp_async4(dst + 32, src + 32);
            if (lane < 17) cp_async4(dst + 64, src + 64);
        }
    };
    // in-place tf32 conversion of one weight buffer (32x92 = 736 float4)
    auto wconv = [&](int buf) {
        float4* v4p = (float4*)&w_s[buf][0][0];
        for (int idx = t; idx < 736; idx += 256)
            v4p[idx] = cvt4(v4p[idx]);
    };

    // --- stage x tile ONCE: xt[b][r][c] = x[b][row_i+r][j0+c], r<9, c<18 ---
    for (int idx = t; idx < B64 * 9 * 18; idx += 256) {
        int b   = idx / 162;
        int rem = idx - b * 162;
        int r   = rem / 18;
        int c   = rem - r * 18;
        cp_async4(&xt[b * XBP + r * XRP + c],
                  x + b * 16384 + (row_i + r) * 128 + j0 + c);
    }
    cp_commit();           // G: xtile
    wpre(p0, 0);
    cp_commit();           // G: W(0)

    // wait for xtile, convert it in place once (pads are zero; cvt(0)=0)
    asm volatile("cp.async.wait_group 1;");
    __syncthreads();
    {
        float4* v4p = (float4*)xt;
        for (int idx = t; idx < (B64 * XBP) / 4; idx += 256)
            v4p[idx] = cvt4(v4p[idx]);
    }

    for (int n = 0; n < PPB; n++) {
        int p   = p0 + n;
        int buf = n & 1;

        if (n + 1 < PPB) {
            wpre(p + 1, buf ^ 1);
            cp_commit();                               // W(n+1)
            asm volatile("cp.async.wait_group 1;");    // W(n) done
        } else {
            asm volatile("cp.async.wait_group 0;");
        }
        __syncthreads();

        // convert this pixel's weight buffer in place (other buffer is
        // being filled by cp.async — disjoint region)
        wconv(buf);
        __syncthreads();

        float d[2][4];     // [n-tile local][frag]
#pragma unroll
        for (int nl = 0; nl < 2; nl++)
#pragma unroll
            for (int r = 0; r < 4; r++) d[nl][r] = 0.f;

        const float (*wb)[PITCH] = w_s[buf];
        const float* pbase = xt + (16 * mt + g) * XBP + n;

#pragma unroll
        for (int kt = 0; kt < 11; kt++) {
            int k0 = kt * 8;
            uint32_t a0 = __float_as_uint(pbase[offA1[kt]]);
            uint32_t a1 = __float_as_uint(pbase[8 * XBP + offA1[kt]]);
            uint32_t a2 = __float_as_uint(pbase[offA2[kt]]);
            uint32_t a3 = __float_as_uint(pbase[8 * XBP + offA2[kt]]);
#pragma unroll
            for (int nl = 0; nl < 2; nl++) {
                int nt = 2 * nh + nl;
                uint32_t b0 = __float_as_uint(wb[8 * nt + g][k0 + q]);
                uint32_t b1 = __float_as_uint(wb[8 * nt + g][k0 + q + 4]);
                asm volatile(
                    "mma.sync.aligned.m16n8k8.row.col.f32.tf32.tf32.f32 "
                    "{%0,%1,%2,%3}, {%4,%5,%6,%7}, {%8,%9}, {%0,%1,%2,%3};"
                    : "+f"(d[nl][0]), "+f"(d[nl][1]), "+f"(d[nl][2]), "+f"(d[nl][3])
                    : "r"(a0), "r"(a1), "r"(a2), "r"(a3), "r"(b0), "r"(b1));
            }
        }
        __syncthreads();   // all reads of w_s[buf] complete

        // relu + phase-mean: s = 4nh + 2nl + (q>>1)
#pragma unroll
        for (int nl = 0; nl < 2; nl++) {
            float r01 = fmaxf(d[nl][0], 0.f) + fmaxf(d[nl][1], 0.f);
            float r23 = fmaxf(d[nl][2], 0.f) + fmaxf(d[nl][3], 0.f);
            r01 += __shfl_xor_sync(0xFFFFFFFFu, r01, 1);
            r23 += __shfl_xor_sync(0xFFFFFFFFu, r23, 1);
            if ((lane & 1) == 0) {
                int s = 4 * nh + 2 * nl + (q >> 1);
                int b = 16 * mt + g;
                bounce[s * 64 + b]     = r01 * 0.25f;
                bounce[s * 64 + b + 8] = r23 * 0.25f;
            }
        }
        __syncthreads();

        // coalesced store: 8 orient x 64 batch (first 128 threads)
        if (t < 128) {
            int s2i = t >> 4;
            int m   = t & 15;
            float4 v = *(const float4*)&bounce[s2i * 64 + m * 4];
            *(float4*)&g_cplx[(s2i * NPIX + p) * B64 + m * 4] = v;
        }
        __syncthreads();
    }
}

#define V1_SMEM ((2 * 32 * PITCH + B64 * XBP + 8 * 64) * 4)

// ---------------------------------------------------------------------------
// V4 via mma.sync m16n8k8 tf32 + fused decision fold (R11-R14 verbatim).
// ---------------------------------------------------------------------------
__global__ __launch_bounds__(128)
void v4_kernel(const float* __restrict__ vw, const float* __restrict__ dw)
{
    extern __shared__ __align__(16) float vsm[];
    float* wt   = vsm;            // [2][16][68]
    float* ps   = vsm + 2176;     // [2][64][72]
    float* dwv  = vsm + 11392;    // [2][16]
    float* part = vsm + 11424;    // [128]

    int p  = blockIdx.x;
    int ii = p / 29;
    int jj = p - ii * 29;
    int base_pix = (ii * 4) * DIMS + jj * 4;

    int t = threadIdx.x;
    int lane = t & 31, wid = t >> 5;
    int g = lane >> 2;
    int q = lane & 3;

    if (t < 32)
        dwv[t] = dw[(t >> 4) * FLATN + (t & 15) * V4PIX + p];

    auto stage_w = [&](int s, int buf) {
        if (t < 64) {
            int o = t >> 2, c4 = t & 3;
            const float* src = vw + (((o << 3) + s) * V4PIX + p) * 64 + c4 * 16;
            float* dst = &wt[buf * 1088 + o * 68 + c4 * 16];
#pragma unroll
            for (int j = 0; j < 4; j++)
                cp_async16(dst + j * 4, src + j * 4);
        }
    };
    auto stage_p = [&](int s, int buf) {
#pragma unroll
        for (int f0 = 0; f0 < 8; f0++) {
            int f = t + f0 * 128;
            int pos = f >> 4, bq = f & 15;
            int di = pos >> 3, dj = pos & 7;
            const float* src = g_cplx + (size_t)s * (NPIX * B64)
                             + (base_pix + di * DIMS + dj) * B64 + bq * 4;
            cp_async16(&ps[buf * 4608 + pos * 72 + bq * 4], src);
        }
    };

    float d[2][4];
#pragma unroll
    for (int n = 0; n < 2; n++)
#pragma unroll
        for (int r = 0; r < 4; r++) d[n][r] = 0.f;

    stage_w(0, 0);
    stage_p(0, 0);
    cp_commit();

    for (int s = 0; s < 8; s++) {
        int buf = s & 1;
        if (s < 7) {
            stage_w(s + 1, buf ^ 1);
            stage_p(s + 1, buf ^ 1);
            cp_commit();
            asm volatile("cp.async.wait_group 1;");
        } else {
            asm volatile("cp.async.wait_group 0;");
        }
        __syncthreads();

        const float* wb = &wt[buf * 1088];
        const float* pb = &ps[buf * 4608];

#pragma unroll
        for (int kt = 0; kt < 8; kt++) {
            int k0 = kt * 8;
            uint32_t a0 = to_tf32(wb[g * 68 + k0 + q]);
            uint32_t a1 = to_tf32(wb[(g + 8) * 68 + k0 + q]);
            uint32_t a2 = to_tf32(wb[g * 68 + k0 + q + 4]);
            uint32_t a3 = to_tf32(wb[(g + 8) * 68 + k0 + q + 4]);
#pragma unroll
            for (int nl = 0; nl < 2; nl++) {
                int nt = 2 * wid + nl;
                uint32_t b0 = to_tf32(pb[(k0 + q) * 72 + 8 * nt + g]);
                uint32_t b1 = to_tf32(pb[(k0 + q + 4) * 72 + 8 * nt + g]);
                asm volatile(
                    "mma.sync.aligned.m16n8k8.row.col.f32.tf32.tf32.f32 "
                    "{%0,%1,%2,%3}, {%4,%5,%6,%7}, {%8,%9}, {%0,%1,%2,%3};"
                    : "+f"(d[nl][0]), "+f"(d[nl][1]), "+f"(d[nl][2]), "+f"(d[nl][3])
                    : "r"(a0), "r"(a1), "r"(a2), "r"(a3), "r"(b0), "r"(b1));
            }
        }
        __syncthreads();
    }

    float dw0g = dwv[g],      dw0h = dwv[g + 8];
    float dw1g = dwv[16 + g], dw1h = dwv[16 + g + 8];
#pragma unroll
    for (int nl = 0; nl < 2; nl++) {
        int nt = 2 * wid + nl;
        float c00 = d[nl][0] * dw0g + d[nl][2] * dw0h;
        float c01 = d[nl][1] * dw0g + d[nl][3] * dw0h;
        float c10 = d[nl][0] * dw1g + d[nl][2] * dw1h;
        float c11 = d[nl][1] * dw1g + d[nl][3] * dw1h;
#pragma unroll
        for (int m = 4; m < 32; m <<= 1) {
            c00 += __shfl_xor_sync(0xFFFFFFFFu, c00, m);
            c01 += __shfl_xor_sync(0xFFFFFFFFu, c01, m);
            c10 += __shfl_xor_sync(0xFFFFFFFFu, c10, m);
            c11 += __shfl_xor_sync(0xFFFFFFFFu, c11, m);
        }
        if (g == 0) {
            int b = 8 * nt + 2 * q;
            part[b * 2 + 0]       = c00;
            part[(b + 1) * 2 + 0] = c01;
            part[b * 2 + 1]       = c10;
            part[(b + 1) * 2 + 1] = c11;
        }
    }
    __syncthreads();
    g_part[p * 128 + t] = part[t];
}
#define V4_SMEM (11552 * 4)

// ---------------------------------------------------------------------------
// dec2: parallel deterministic reduction (R11-R14 verbatim).
// ---------------------------------------------------------------------------
__global__ __launch_bounds__(256)
void dec2_kernel(const float* __restrict__ db, float* __restrict__ out)
{
    int t = blockIdx.x;          // output index b*2+cls
    int j = threadIdx.x;

    float ssum = 0.f;
    for (int p = j; p < V4PIX; p += 256)
        ssum += g_part[p * 128 + t];

    __shared__ float red[256];
    red[j] = ssum;
    __syncthreads();
    for (int off = 128; off > 0; off >>= 1) {
        if (j < off) red[j] += red[j + off];
        __syncthreads();
    }
    if (j == 0) out[t] = red[0] + db[t & 1];
}

// ---------------------------------------------------------------------------
extern "C" void kernel_launch(void* const* d_in, const int* in_sizes, int n_in,
                              void* d_out, int out_size)
{
    const float* x  = (const float*)d_in[0];   // [64,1,128,128]
    const float* sw = (const float*)d_in[1];   // [32,120,120,81]
    const float* vw = (const float*)d_in[2];   // [16,8,29,29,64]
    const float* dw = (const float*)d_in[3];   // [2,13456]
    const float* db = (const float*)d_in[4];   // [2]
    float* out = (float*)d_out;                // [64,2]

    cudaFuncSetAttribute(v1_kernel, cudaFuncAttributeMaxDynamicSharedMemorySize, V1_SMEM);
    cudaFuncSetAttribute(v4_kernel, cudaFuncAttributeMaxDynamicSharedMemorySize, V4_SMEM);

    v1_kernel<<<NPIX / PPB, 256, V1_SMEM>>>(x, sw);
    v4_kernel<<<V4PIX, 128, V4_SMEM>>>(vw, dw);
    dec2_kernel<<<128, 256>>>(db, out);
}

// round 16
// speedup vs baseline: 1.1004x; 1.1004x over previous
#include <cuda_runtime.h>
#include <cstdint>

#define DIMS   120
#define NPIX   14400        // 120*120
#define SS2    81
#define B64    64
#define PITCH  92           // weights: banks 28g+q all-distinct
#define XBP    210          // x-tile batch pitch (10 rows x 21)
#define XRP    21           // x-tile row pitch
#define V4PIX  841          // 29*29
#define FLATN  13456        // 16*841
#define PPB    10           // pixels per v1 block (same image row)

// Intermediates (allocation-free scratch)
__device__ float g_cplx[8 * NPIX * B64];    // [s][pix][b]
__device__ float g_part[V4PIX * 128];       // [p][b*2+cls] decision partials

__device__ __forceinline__ void cp_async4(void* smem_dst, const void* gmem_src) {
    unsigned s = (unsigned)__cvta_generic_to_shared(smem_dst);
    asm volatile("cp.async.ca.shared.global [%0], [%1], 4;" :: "r"(s), "l"(gmem_src));
}
__device__ __forceinline__ void cp_async16(void* smem_dst, const void* gmem_src) {
    unsigned s = (unsigned)__cvta_generic_to_shared(smem_dst);
    asm volatile("cp.async.cg.shared.global [%0], [%1], 16;" :: "r"(s), "l"(gmem_src));
}
__device__ __forceinline__ void cp_commit() {
    asm volatile("cp.async.commit_group;");
}
__device__ __forceinline__ uint32_t to_tf32(float f) {
    uint32_t r;
    asm("cvt.rna.tf32.f32 %0, %1;" : "=r"(r) : "f"(f));
    return r;
}
__device__ __forceinline__ float4 cvt4(float4 v) {
    float4 o;
    o.x = __uint_as_float(to_tf32(v.x));
    o.y = __uint_as_float(to_tf32(v.y));
    o.z = __uint_as_float(to_tf32(v.z));
    o.w = __uint_as_float(to_tf32(v.w));
    return o;
}

// ---------------------------------------------------------------------------
// V1 via mma.sync m16n8k8 tf32, 256 threads (R14 structure, measured 101.9us)
// + ONE change: the x-tile is pre-converted to tf32 once per block, removing
// 44 A-side cvt instructions per warp per pixel. Weight cvts remain in the
// GEMM loop exactly as in R14 (no per-pixel conversion pass / extra sync).
// Warp w: m-tile = w>>1 (batches 16mt..), n-half = w&1 (n-tiles 2nh,2nh+1).
// ---------------------------------------------------------------------------
__global__ __launch_bounds__(256)
void v1_kernel(const float* __restrict__ x, const float* __restrict__ w)
{
    extern __shared__ __align__(16) float sm[];
    float (*w_s)[32][PITCH] = (float (*)[32][PITCH])sm;         // [2][32][92]
    float* xt               = sm + 2 * 32 * PITCH;              // [64][210]
    float* bounce           = sm + 2 * 32 * PITCH + B64 * XBP;  // [8*64]

    int t = threadIdx.x;
    int lane = t & 31, wid = t >> 5;
    int g = lane >> 2;
    int q = lane & 3;
    int mt = wid >> 1;          // m-tile (batch group)
    int nh = wid & 1;           // n-half

    int row_i = blockIdx.x / 12;
    int j0    = (blockIdx.x % 12) * 10;
    int p0    = row_i * DIMS + j0;

    // zero weight k-padding cols 81..91 (both buffers)
    if (t < 64) {
        float* rowp = &w_s[t >> 5][t & 31][0];
#pragma unroll
        for (int c = 81; c < 92; c++) rowp[c] = 0.f;
    }
    // zero x-tile pad row r=9
    for (int idx = t; idx < B64 * XRP; idx += 256)
        xt[(idx / XRP) * XBP + 9 * XRP + (idx % XRP)] = 0.f;

    // per-thread A-fragment offsets: offA(k) = (k/9)*21 + k%9
    int offA1[11], offA2[11];
#pragma unroll
    for (int kt = 0; kt < 11; kt++) {
        int k1 = kt * 8 + q;
        int k2 = k1 + 4;
        offA1[kt] = (k1 / 9) * XRP + (k1 % 9);
        offA2[kt] = (k2 / 9) * XRP + (k2 % 9);
    }

    // weight staging: pixel p -> w_s[buf][c][k]; 8 warps x 4 channels
    auto wpre = [&](int p, int buf) {
#pragma unroll
        for (int gg = 0; gg < 4; gg++) {
            int c = wid * 4 + gg;
            const float* src = w + (c * NPIX + p) * SS2 + lane;
            float* dst = &w_s[buf][c][lane];
            cp_async4(dst, src);
            cp_async4(dst + 32, src + 32);
            if (lane < 17) cp_async4(dst + 64, src + 64);
        }
    };

    // --- stage x tile ONCE: xt[b][r][c] = x[b][row_i+r][j0+c], r<9, c<18 ---
    for (int idx = t; idx < B64 * 9 * 18; idx += 256) {
        int b   = idx / 162;
        int rem = idx - b * 162;
        int r   = rem / 18;
        int c   = rem - r * 18;
        cp_async4(&xt[b * XBP + r * XRP + c],
                  x + b * 16384 + (row_i + r) * 128 + j0 + c);
    }
    cp_commit();           // G: xtile
    wpre(p0, 0);
    cp_commit();           // G: W(0)

    // wait for xtile, convert it in place once (pads are zero; cvt(0)=0)
    asm volatile("cp.async.wait_group 1;");
    __syncthreads();
    {
        float4* v4p = (float4*)xt;
        for (int idx = t; idx < (B64 * XBP) / 4; idx += 256)
            v4p[idx] = cvt4(v4p[idx]);
    }

    for (int n = 0; n < PPB; n++) {
        int p   = p0 + n;
        int buf = n & 1;

        if (n + 1 < PPB) {
            wpre(p + 1, buf ^ 1);
            cp_commit();                               // W(n+1)
            asm volatile("cp.async.wait_group 1;");    // W(n) done
        } else {
            asm volatile("cp.async.wait_group 0;");
        }
        __syncthreads();

        float d[2][4];     // [n-tile local][frag]
#pragma unroll
        for (int nl = 0; nl < 2; nl++)
#pragma unroll
            for (int r = 0; r < 4; r++) d[nl][r] = 0.f;

        const float (*wb)[PITCH] = w_s[buf];
        const float* pbase = xt + (16 * mt + g) * XBP + n;

#pragma unroll
        for (int kt = 0; kt < 11; kt++) {
            int k0 = kt * 8;
            uint32_t a0 = __float_as_uint(pbase[offA1[kt]]);
            uint32_t a1 = __float_as_uint(pbase[8 * XBP + offA1[kt]]);
            uint32_t a2 = __float_as_uint(pbase[offA2[kt]]);
            uint32_t a3 = __float_as_uint(pbase[8 * XBP + offA2[kt]]);
#pragma unroll
            for (int nl = 0; nl < 2; nl++) {
                int nt = 2 * nh + nl;
                uint32_t b0 = to_tf32(wb[8 * nt + g][k0 + q]);
                uint32_t b1 = to_tf32(wb[8 * nt + g][k0 + q + 4]);
                asm volatile(
                    "mma.sync.aligned.m16n8k8.row.col.f32.tf32.tf32.f32 "
                    "{%0,%1,%2,%3}, {%4,%5,%6,%7}, {%8,%9}, {%0,%1,%2,%3};"
                    : "+f"(d[nl][0]), "+f"(d[nl][1]), "+f"(d[nl][2]), "+f"(d[nl][3])
                    : "r"(a0), "r"(a1), "r"(a2), "r"(a3), "r"(b0), "r"(b1));
            }
        }
        __syncthreads();   // all reads of w_s[buf] complete

        // relu + phase-mean: s = 4nh + 2nl + (q>>1)
#pragma unroll
        for (int nl = 0; nl < 2; nl++) {
            float r01 = fmaxf(d[nl][0], 0.f) + fmaxf(d[nl][1], 0.f);
            float r23 = fmaxf(d[nl][2], 0.f) + fmaxf(d[nl][3], 0.f);
            r01 += __shfl_xor_sync(0xFFFFFFFFu, r01, 1);
            r23 += __shfl_xor_sync(0xFFFFFFFFu, r23, 1);
            if ((lane & 1) == 0) {
                int s = 4 * nh + 2 * nl + (q >> 1);
                int b = 16 * mt + g;
                bounce[s * 64 + b]     = r01 * 0.25f;
                bounce[s * 64 + b + 8] = r23 * 0.25f;
            }
        }
        __syncthreads();

        // coalesced store: 8 orient x 64 batch (first 128 threads)
        if (t < 128) {
            int s2i = t >> 4;
            int m   = t & 15;
            float4 v = *(const float4*)&bounce[s2i * 64 + m * 4];
            *(float4*)&g_cplx[(s2i * NPIX + p) * B64 + m * 4] = v;
        }
        __syncthreads();
    }
}

#define V1_SMEM ((2 * 32 * PITCH + B64 * XBP + 8 * 64) * 4)

// ---------------------------------------------------------------------------
// V4 via mma.sync m16n8k8 tf32 + fused decision fold (R11-R15 verbatim).
// ---------------------------------------------------------------------------
__global__ __launch_bounds__(128)
void v4_kernel(const float* __restrict__ vw, const float* __restrict__ dw)
{
    extern __shared__ __align__(16) float vsm[];
    float* wt   = vsm;            // [2][16][68]
    float* ps   = vsm + 2176;     // [2][64][72]
    float* dwv  = vsm + 11392;    // [2][16]
    float* part = vsm + 11424;    // [128]

    int p  = blockIdx.x;
    int ii = p / 29;
    int jj = p - ii * 29;
    int base_pix = (ii * 4) * DIMS + jj * 4;

    int t = threadIdx.x;
    int lane = t & 31, wid = t >> 5;
    int g = lane >> 2;
    int q = lane & 3;

    if (t < 32)
        dwv[t] = dw[(t >> 4) * FLATN + (t & 15) * V4PIX + p];

    auto stage_w = [&](int s, int buf) {
        if (t < 64) {
            int o = t >> 2, c4 = t & 3;
            const float* src = vw + (((o << 3) + s) * V4PIX + p) * 64 + c4 * 16;
            float* dst = &wt[buf * 1088 + o * 68 + c4 * 16];
#pragma unroll
            for (int j = 0; j < 4; j++)
                cp_async16(dst + j * 4, src + j * 4);
        }
    };
    auto stage_p = [&](int s, int buf) {
#pragma unroll
        for (int f0 = 0; f0 < 8; f0++) {
            int f = t + f0 * 128;
            int pos = f >> 4, bq = f & 15;
            int di = pos >> 3, dj = pos & 7;
            const float* src = g_cplx + (size_t)s * (NPIX * B64)
                             + (base_pix + di * DIMS + dj) * B64 + bq * 4;
            cp_async16(&ps[buf * 4608 + pos * 72 + bq * 4], src);
        }
    };

    float d[2][4];
#pragma unroll
    for (int n = 0; n < 2; n++)
#pragma unroll
        for (int r = 0; r < 4; r++) d[n][r] = 0.f;

    stage_w(0, 0);
    stage_p(0, 0);
    cp_commit();

    for (int s = 0; s < 8; s++) {
        int buf = s & 1;
        if (s < 7) {
            stage_w(s + 1, buf ^ 1);
            stage_p(s + 1, buf ^ 1);
            cp_commit();
            asm volatile("cp.async.wait_group 1;");
        } else {
            asm volatile("cp.async.wait_group 0;");
        }
        __syncthreads();

        const float* wb = &wt[buf * 1088];
        const float* pb = &ps[buf * 4608];

#pragma unroll
        for (int kt = 0; kt < 8; kt++) {
            int k0 = kt * 8;
            uint32_t a0 = to_tf32(wb[g * 68 + k0 + q]);
            uint32_t a1 = to_tf32(wb[(g + 8) * 68 + k0 + q]);
            uint32_t a2 = to_tf32(wb[g * 68 + k0 + q + 4]);
            uint32_t a3 = to_tf32(wb[(g + 8) * 68 + k0 + q + 4]);
#pragma unroll
            for (int nl = 0; nl < 2; nl++) {
                int nt = 2 * wid + nl;
                uint32_t b0 = to_tf32(pb[(k0 + q) * 72 + 8 * nt + g]);
                uint32_t b1 = to_tf32(pb[(k0 + q + 4) * 72 + 8 * nt + g]);
                asm volatile(
                    "mma.sync.aligned.m16n8k8.row.col.f32.tf32.tf32.f32 "
                    "{%0,%1,%2,%3}, {%4,%5,%6,%7}, {%8,%9}, {%0,%1,%2,%3};"
                    : "+f"(d[nl][0]), "+f"(d[nl][1]), "+f"(d[nl][2]), "+f"(d[nl][3])
                    : "r"(a0), "r"(a1), "r"(a2), "r"(a3), "r"(b0), "r"(b1));
            }
        }
        __syncthreads();
    }

    float dw0g = dwv[g],      dw0h = dwv[g + 8];
    float dw1g = dwv[16 + g], dw1h = dwv[16 + g + 8];
#pragma unroll
    for (int nl = 0; nl < 2; nl++) {
        int nt = 2 * wid + nl;
        float c00 = d[nl][0] * dw0g + d[nl][2] * dw0h;
        float c01 = d[nl][1] * dw0g + d[nl][3] * dw0h;
        float c10 = d[nl][0] * dw1g + d[nl][2] * dw1h;
        float c11 = d[nl][1] * dw1g + d[nl][3] * dw1h;
#pragma unroll
        for (int m = 4; m < 32; m <<= 1) {
            c00 += __shfl_xor_sync(0xFFFFFFFFu, c00, m);
            c01 += __shfl_xor_sync(0xFFFFFFFFu, c01, m);
            c10 += __shfl_xor_sync(0xFFFFFFFFu, c10, m);
            c11 += __shfl_xor_sync(0xFFFFFFFFu, c11, m);
        }
        if (g == 0) {
            int b = 8 * nt + 2 * q;
            part[b * 2 + 0]       = c00;
            part[(b + 1) * 2 + 0] = c01;
            part[b * 2 + 1]       = c10;
            part[(b + 1) * 2 + 1] = c11;
        }
    }
    __syncthreads();
    g_part[p * 128 + t] = part[t];
}
#define V4_SMEM (11552 * 4)

// ---------------------------------------------------------------------------
// dec2: parallel deterministic reduction (R11-R15 verbatim).
// ---------------------------------------------------------------------------
__global__ __launch_bounds__(256)
void dec2_kernel(const float* __restrict__ db, float* __restrict__ out)
{
    int t = blockIdx.x;          // output index b*2+cls
    int j = threadIdx.x;

    float ssum = 0.f;
    for (int p = j; p < V4PIX; p += 256)
        ssum += g_part[p * 128 + t];

    __shared__ float red[256];
    red[j] = ssum;
    __syncthreads();
    for (int off = 128; off > 0; off >>= 1) {
        if (j < off) red[j] += red[j + off];
        __syncthreads();
    }
    if (j == 0) out[t] = red[0] + db[t & 1];
}

// ---------------------------------------------------------------------------
extern "C" void kernel_launch(void* const* d_in, const int* in_sizes, int n_in,
                              void* d_out, int out_size)
{
    const float* x  = (const float*)d_in[0];   // [64,1,128,128]
    const float* sw = (const float*)d_in[1];   // [32,120,120,81]
    const float* vw = (const float*)d_in[2];   // [16,8,29,29,64]
    const float* dw = (const float*)d_in[3];   // [2,13456]
    const float* db = (const float*)d_in[4];   // [2]
    float* out = (float*)d_out;                // [64,2]

    cudaFuncSetAttribute(v1_kernel, cudaFuncAttributeMaxDynamicSharedMemorySize, V1_SMEM);
    cudaFuncSetAttribute(v4_kernel, cudaFuncAttributeMaxDynamicSharedMemorySize, V4_SMEM);

    v1_kernel<<<NPIX / PPB, 256, V1_SMEM>>>(x, sw);
    v4_kernel<<<V4PIX, 128, V4_SMEM>>>(vw, dw);
    dec2_kernel<<<128, 256>>>(db, out);
}

// round 17
// speedup vs baseline: 1.1265x; 1.0237x over previous
#include <cuda_runtime.h>
#include <cstdint>

#define DIMS   120
#define NPIX   14400        // 120*120
#define SS2    81
#define B64    64
#define PITCH  92           // weights: banks 28g+q all-distinct
#define XBP    210          // x-tile batch pitch (10 rows x 21)
#define XRP    21           // x-tile row pitch
#define V4PIX  841          // 29*29
#define FLATN  13456        // 16*841
#define PPB    10           // pixels per v1 block (same image row)

// Intermediates (allocation-free scratch)
__device__ float g_cplx[8 * NPIX * B64];    // [s][pix][b]
__device__ float g_part[V4PIX * 128];       // [p][b*2+cls] decision partials

__device__ __forceinline__ void cp_async4(void* smem_dst, const void* gmem_src) {
    unsigned s = (unsigned)__cvta_generic_to_shared(smem_dst);
    asm volatile("cp.async.ca.shared.global [%0], [%1], 4;" :: "r"(s), "l"(gmem_src));
}
__device__ __forceinline__ void cp_async16(void* smem_dst, const void* gmem_src) {
    unsigned s = (unsigned)__cvta_generic_to_shared(smem_dst);
    asm volatile("cp.async.cg.shared.global [%0], [%1], 16;" :: "r"(s), "l"(gmem_src));
}
__device__ __forceinline__ void cp_commit() {
    asm volatile("cp.async.commit_group;");
}
__device__ __forceinline__ uint32_t to_tf32(float f) {
    uint32_t r;
    asm("cvt.rna.tf32.f32 %0, %1;" : "=r"(r) : "f"(f));
    return r;
}

// ---------------------------------------------------------------------------
// V1 via mma.sync m16n8k8 tf32, 256 threads (R14 verbatim, measured 101.9us).
// x-tile staged once per block; A-fragments via precomputed offsets;
// weights double-buffered via cp.async; cvts in the GEMM loop.
// Warp w: m-tile = w>>1, n-half = w&1.
// ---------------------------------------------------------------------------
__global__ __launch_bounds__(256)
void v1_kernel(const float* __restrict__ x, const float* __restrict__ w)
{
    extern __shared__ __align__(16) float sm[];
    float (*w_s)[32][PITCH] = (float (*)[32][PITCH])sm;         // [2][32][92]
    float* xt               = sm + 2 * 32 * PITCH;              // [64][210]
    float* bounce           = sm + 2 * 32 * PITCH + B64 * XBP;  // [8*64]

    int t = threadIdx.x;
    int lane = t & 31, wid = t >> 5;
    int g = lane >> 2;
    int q = lane & 3;
    int mt = wid >> 1;          // m-tile (batch group)
    int nh = wid & 1;           // n-half

    int row_i = blockIdx.x / 12;
    int j0    = (blockIdx.x % 12) * 10;
    int p0    = row_i * DIMS + j0;

    // zero weight k-padding cols 81..91 (both buffers)
    if (t < 64) {
        float* rowp = &w_s[t >> 5][t & 31][0];
#pragma unroll
        for (int c = 81; c < 92; c++) rowp[c] = 0.f;
    }
    // zero x-tile pad row r=9
    for (int idx = t; idx < B64 * XRP; idx += 256)
        xt[(idx / XRP) * XBP + 9 * XRP + (idx % XRP)] = 0.f;

    // per-thread A-fragment offsets: offA(k) = (k/9)*21 + k%9
    int offA1[11], offA2[11];
#pragma unroll
    for (int kt = 0; kt < 11; kt++) {
        int k1 = kt * 8 + q;
        int k2 = k1 + 4;
        offA1[kt] = (k1 / 9) * XRP + (k1 % 9);
        offA2[kt] = (k2 / 9) * XRP + (k2 % 9);
    }

    // weight staging: pixel p -> w_s[buf][c][k]; 8 warps x 4 channels
    auto wpre = [&](int p, int buf) {
#pragma unroll
        for (int gg = 0; gg < 4; gg++) {
            int c = wid * 4 + gg;
            const float* src = w + (c * NPIX + p) * SS2 + lane;
            float* dst = &w_s[buf][c][lane];
            cp_async4(dst, src);
            cp_async4(dst + 32, src + 32);
            if (lane < 17) cp_async4(dst + 64, src + 64);
        }
    };

    // --- stage x tile ONCE: xt[b][r][c] = x[b][row_i+r][j0+c], r<9, c<18 ---
    for (int idx = t; idx < B64 * 9 * 18; idx += 256) {
        int b   = idx / 162;
        int rem = idx - b * 162;
        int r   = rem / 18;
        int c   = rem - r * 18;
        cp_async4(&xt[b * XBP + r * XRP + c],
                  x + b * 16384 + (row_i + r) * 128 + j0 + c);
    }
    cp_commit();           // G: xtile
    wpre(p0, 0);
    cp_commit();           // G: W(0)

    for (int n = 0; n < PPB; n++) {
        int p   = p0 + n;
        int buf = n & 1;

        if (n + 1 < PPB) {
            wpre(p + 1, buf ^ 1);
            cp_commit();                               // W(n+1)
            asm volatile("cp.async.wait_group 1;");    // xtile/W(n) done
        } else {
            asm volatile("cp.async.wait_group 0;");
        }
        __syncthreads();

        float d[2][4];     // [n-tile local][frag]
#pragma unroll
        for (int nl = 0; nl < 2; nl++)
#pragma unroll
            for (int r = 0; r < 4; r++) d[nl][r] = 0.f;

        const float (*wb)[PITCH] = w_s[buf];
        const float* pbase = xt + (16 * mt + g) * XBP + n;

#pragma unroll
        for (int kt = 0; kt < 11; kt++) {
            int k0 = kt * 8;
            uint32_t a0 = to_tf32(pbase[offA1[kt]]);
            uint32_t a1 = to_tf32(pbase[8 * XBP + offA1[kt]]);
            uint32_t a2 = to_tf32(pbase[offA2[kt]]);
            uint32_t a3 = to_tf32(pbase[8 * XBP + offA2[kt]]);
#pragma unroll
            for (int nl = 0; nl < 2; nl++) {
                int nt = 2 * nh + nl;
                uint32_t b0 = to_tf32(wb[8 * nt + g][k0 + q]);
                uint32_t b1 = to_tf32(wb[8 * nt + g][k0 + q + 4]);
                asm volatile(
                    "mma.sync.aligned.m16n8k8.row.col.f32.tf32.tf32.f32 "
                    "{%0,%1,%2,%3}, {%4,%5,%6,%7}, {%8,%9}, {%0,%1,%2,%3};"
                    : "+f"(d[nl][0]), "+f"(d[nl][1]), "+f"(d[nl][2]), "+f"(d[nl][3])
                    : "r"(a0), "r"(a1), "r"(a2), "r"(a3), "r"(b0), "r"(b1));
            }
        }
        __syncthreads();   // all reads of w_s[buf] complete

        // relu + phase-mean: s = 4nh + 2nl + (q>>1)
#pragma unroll
        for (int nl = 0; nl < 2; nl++) {
            float r01 = fmaxf(d[nl][0], 0.f) + fmaxf(d[nl][1], 0.f);
            float r23 = fmaxf(d[nl][2], 0.f) + fmaxf(d[nl][3], 0.f);
            r01 += __shfl_xor_sync(0xFFFFFFFFu, r01, 1);
            r23 += __shfl_xor_sync(0xFFFFFFFFu, r23, 1);
            if ((lane & 1) == 0) {
                int s = 4 * nh + 2 * nl + (q >> 1);
                int b = 16 * mt + g;
                bounce[s * 64 + b]     = r01 * 0.25f;
                bounce[s * 64 + b + 8] = r23 * 0.25f;
            }
        }
        __syncthreads();

        // coalesced store: 8 orient x 64 batch (first 128 threads)
        if (t < 128) {
            int s2i = t >> 4;
            int m   = t & 15;
            float4 v = *(const float4*)&bounce[s2i * 64 + m * 4];
            *(float4*)&g_cplx[(s2i * NPIX + p) * B64 + m * 4] = v;
        }
        __syncthreads();
    }
}

#define V1_SMEM ((2 * 32 * PITCH + B64 * XBP + 8 * 64) * 4)

// ---------------------------------------------------------------------------
// V4 via mma.sync m16n8k8 tf32 + fused decision fold — 256 threads.
// Warp w (0..7) owns n-tile nt = w (batches 8w..8w+7). Per-warp work halves
// vs the 128-thread version; warps/SM double (32) at unchanged smem for
// latency hiding. Bank maps unchanged (A: 4g+q, B: 8q+g, both full).
// ---------------------------------------------------------------------------
__global__ __launch_bounds__(256)
void v4_kernel(const float* __restrict__ vw, const float* __restrict__ dw)
{
    extern __shared__ __align__(16) float vsm[];
    float* wt   = vsm;            // [2][16][68]
    float* ps   = vsm + 2176;     // [2][64][72]
    float* dwv  = vsm + 11392;    // [2][16]
    float* part = vsm + 11424;    // [128]

    int p  = blockIdx.x;
    int ii = p / 29;
    int jj = p - ii * 29;
    int base_pix = (ii * 4) * DIMS + jj * 4;

    int t = threadIdx.x;
    int lane = t & 31, wid = t >> 5;
    int g = lane >> 2;
    int q = lane & 3;

    if (t < 32)
        dwv[t] = dw[(t >> 4) * FLATN + (t & 15) * V4PIX + p];

    auto stage_w = [&](int s, int buf) {
        if (t < 64) {
            int o = t >> 2, c4 = t & 3;
            const float* src = vw + (((o << 3) + s) * V4PIX + p) * 64 + c4 * 16;
            float* dst = &wt[buf * 1088 + o * 68 + c4 * 16];
#pragma unroll
            for (int j = 0; j < 4; j++)
                cp_async16(dst + j * 4, src + j * 4);
        }
    };
    auto stage_p = [&](int s, int buf) {
#pragma unroll
        for (int f0 = 0; f0 < 4; f0++) {
            int f = t + f0 * 256;
            int pos = f >> 4, bq = f & 15;
            int di = pos >> 3, dj = pos & 7;
            const float* src = g_cplx + (size_t)s * (NPIX * B64)
                             + (base_pix + di * DIMS + dj) * B64 + bq * 4;
            cp_async16(&ps[buf * 4608 + pos * 72 + bq * 4], src);
        }
    };

    float d[4];
#pragma unroll
    for (int r = 0; r < 4; r++) d[r] = 0.f;

    stage_w(0, 0);
    stage_p(0, 0);
    cp_commit();

    for (int s = 0; s < 8; s++) {
        int buf = s & 1;
        if (s < 7) {
            stage_w(s + 1, buf ^ 1);
            stage_p(s + 1, buf ^ 1);
            cp_commit();
            asm volatile("cp.async.wait_group 1;");
        } else {
            asm volatile("cp.async.wait_group 0;");
        }
        __syncthreads();

        const float* wb = &wt[buf * 1088];
        const float* pb = &ps[buf * 4608];

#pragma unroll
        for (int kt = 0; kt < 8; kt++) {
            int k0 = kt * 8;
            uint32_t a0 = to_tf32(wb[g * 68 + k0 + q]);
            uint32_t a1 = to_tf32(wb[(g + 8) * 68 + k0 + q]);
            uint32_t a2 = to_tf32(wb[g * 68 + k0 + q + 4]);
            uint32_t a3 = to_tf32(wb[(g + 8) * 68 + k0 + q + 4]);
            uint32_t b0 = to_tf32(pb[(k0 + q) * 72 + 8 * wid + g]);
            uint32_t b1 = to_tf32(pb[(k0 + q + 4) * 72 + 8 * wid + g]);
            asm volatile(
                "mma.sync.aligned.m16n8k8.row.col.f32.tf32.tf32.f32 "
                "{%0,%1,%2,%3}, {%4,%5,%6,%7}, {%8,%9}, {%0,%1,%2,%3};"
                : "+f"(d[0]), "+f"(d[1]), "+f"(d[2]), "+f"(d[3])
                : "r"(a0), "r"(a1), "r"(a2), "r"(a3), "r"(b0), "r"(b1));
        }
        __syncthreads();
    }

    // fused decision fold: d[0/1] = (o=g, b=8wid+2q+{0,1}),
    //                      d[2/3] = (o=g+8, same b)
    float dw0g = dwv[g],      dw0h = dwv[g + 8];
    float dw1g = dwv[16 + g], dw1h = dwv[16 + g + 8];
    {
        float c00 = d[0] * dw0g + d[2] * dw0h;   // cls0, b even
        float c01 = d[1] * dw0g + d[3] * dw0h;   // cls0, b odd
        float c10 = d[0] * dw1g + d[2] * dw1h;   // cls1, b even
        float c11 = d[1] * dw1g + d[3] * dw1h;   // cls1, b odd
#pragma unroll
        for (int m = 4; m < 32; m <<= 1) {
            c00 += __shfl_xor_sync(0xFFFFFFFFu, c00, m);
            c01 += __shfl_xor_sync(0xFFFFFFFFu, c01, m);
            c10 += __shfl_xor_sync(0xFFFFFFFFu, c10, m);
            c11 += __shfl_xor_sync(0xFFFFFFFFu, c11, m);
        }
        if (g == 0) {
            int b = 8 * wid + 2 * q;
            part[b * 2 + 0]       = c00;
            part[(b + 1) * 2 + 0] = c01;
            part[b * 2 + 1]       = c10;
            part[(b + 1) * 2 + 1] = c11;
        }
    }
    __syncthreads();
    if (t < 128)
        g_part[p * 128 + t] = part[t];
}
#define V4_SMEM (11552 * 4)

// ---------------------------------------------------------------------------
// dec2: parallel deterministic reduction (verbatim).
// ---------------------------------------------------------------------------
__global__ __launch_bounds__(256)
void dec2_kernel(const float* __restrict__ db, float* __restrict__ out)
{
    int t = blockIdx.x;          // output index b*2+cls
    int j = threadIdx.x;

    float ssum = 0.f;
    for (int p = j; p < V4PIX; p += 256)
        ssum += g_part[p * 128 + t];

    __shared__ float red[256];
    red[j] = ssum;
    __syncthreads();
    for (int off = 128; off > 0; off >>= 1) {
        if (j < off) red[j] += red[j + off];
        __syncthreads();
    }
    if (j == 0) out[t] = red[0] + db[t & 1];
}

// ---------------------------------------------------------------------------
extern "C" void kernel_launch(void* const* d_in, const int* in_sizes, int n_in,
                              void* d_out, int out_size)
{
    const float* x  = (const float*)d_in[0];   // [64,1,128,128]
    const float* sw = (const float*)d_in[1];   // [32,120,120,81]
    const float* vw = (const float*)d_in[2];   // [16,8,29,29,64]
    const float* dw = (const float*)d_in[3];   // [2,13456]
    const float* db = (const float*)d_in[4];   // [2]
    float* out = (float*)d_out;                // [64,2]

    cudaFuncSetAttribute(v1_kernel, cudaFuncAttributeMaxDynamicSharedMemorySize, V1_SMEM);
    cudaFuncSetAttribute(v4_kernel, cudaFuncAttributeMaxDynamicSharedMemorySize, V4_SMEM);

    v1_kernel<<<NPIX / PPB, 256, V1_SMEM>>>(x, sw);
    v4_kernel<<<V4PIX, 256, V4_SMEM>>>(vw, dw);
    dec2_kernel<<<128, 256>>>(db, out);
}